// round 1
// baseline (speedup 1.0000x reference)
#include <cuda_runtime.h>
#include <math.h>

#define T_STEPS 4096
#define H_DIM   2048
#define O_DIM   512

#define RNN_CTAS    128
#define RNN_THREADS 256

// ---------------- device scratch (allocation-free rule) ----------------
__device__ float g_xp[(size_t)T_STEPS * H_DIM];   // x @ W_ih^T + b_ih + b_hh
__device__ float g_hs[(size_t)T_STEPS * H_DIM];   // all hidden states h_t
__device__ unsigned g_bar_count;
__device__ volatile unsigned g_bar_gen;

// ---------------- grid-wide sense barrier (128 co-resident CTAs) -------
__device__ __forceinline__ void grid_sync()
{
    __syncthreads();
    if (threadIdx.x == 0) {
        __threadfence();                       // make our h writes visible first
        unsigned gen = g_bar_gen;              // read BEFORE arriving
        unsigned t = atomicAdd(&g_bar_count, 1);
        if (t == RNN_CTAS - 1) {
            g_bar_count = 0;
            __threadfence();
            g_bar_gen = gen + 1;
        } else {
            while (g_bar_gen == gen) { }
            __threadfence();                   // acquire
        }
    }
    __syncthreads();
}

// ---------------- persistent recurrence kernel -------------------------
// h_t = tanh(xp_t + W_hh @ h_{t-1}); W_hh rows live in registers.
// 128 CTAs x 16 rows. 8 warps/CTA, 2 rows/warp, 64 k-elems (16 float4)/lane.
__global__ void __launch_bounds__(RNN_THREADS, 1)
rnn_kernel(const float* __restrict__ W_hh, const float* __restrict__ h0)
{
    __shared__ __align__(16) float hbuf[H_DIM];
    const int tid  = threadIdx.x;
    const int lane = tid & 31;
    const int wid  = tid >> 5;                    // 0..7
    const int r0   = blockIdx.x * 16 + wid * 2;   // this warp's two rows

    // Load this warp's two weight rows into registers.
    // lane l owns k = j*128 + l*4 .. +3 for j in [0,16)
    float4 w0[16], w1[16];
    const float4* W0 = (const float4*)(W_hh + (size_t)r0 * H_DIM);
    const float4* W1 = (const float4*)(W_hh + (size_t)(r0 + 1) * H_DIM);
#pragma unroll
    for (int j = 0; j < 16; j++) {
        w0[j] = __ldg(&W0[j * 32 + lane]);
        w1[j] = __ldg(&W1[j * 32 + lane]);
    }

    for (int t = 0; t < T_STEPS; t++) {
        const float4* hprev = (t == 0)
            ? (const float4*)h0
            : (const float4*)(g_hs + (size_t)(t - 1) * H_DIM);

        // Stage h_{t-1} into shared (L2-coherent loads: written by other SMs).
        float4 a = __ldcg(&hprev[tid]);
        float4 b = __ldcg(&hprev[tid + RNN_THREADS]);

        float xpv0 = 0.f, xpv1 = 0.f;
        if (lane == 0) {
            xpv0 = __ldg(&g_xp[(size_t)t * H_DIM + r0]);
            xpv1 = __ldg(&g_xp[(size_t)t * H_DIM + r0 + 1]);
        }

        ((float4*)hbuf)[tid]               = a;
        ((float4*)hbuf)[tid + RNN_THREADS] = b;
        __syncthreads();

        float acc0 = 0.f, acc1 = 0.f;
#pragma unroll
        for (int j = 0; j < 16; j++) {
            float4 h4 = ((const float4*)hbuf)[j * 32 + lane];  // conflict-free
            acc0 += w0[j].x * h4.x; acc1 += w1[j].x * h4.x;
            acc0 += w0[j].y * h4.y; acc1 += w1[j].y * h4.y;
            acc0 += w0[j].z * h4.z; acc1 += w1[j].z * h4.z;
            acc0 += w0[j].w * h4.w; acc1 += w1[j].w * h4.w;
        }

#pragma unroll
        for (int off = 16; off > 0; off >>= 1) {
            acc0 += __shfl_down_sync(0xffffffffu, acc0, off);
            acc1 += __shfl_down_sync(0xffffffffu, acc1, off);
        }

        if (lane == 0) {
            g_hs[(size_t)t * H_DIM + r0]     = tanhf(xpv0 + acc0);
            g_hs[(size_t)t * H_DIM + r0 + 1] = tanhf(xpv1 + acc1);
        }

        grid_sync();   // publishes h_t; also fences hbuf for next iteration
    }
}

// ---------------- tiled fp32 NT GEMM: C[M,N] = A[M,K] @ B[N,K]^T + bias --
// PHASE 0: A = param (x),   C = g_xp,  bias = b_ih + b_hh
// PHASE 1: A = g_hs,        C = param, bias = b_lin
#define BM 128
#define BN 64
#define BK 16

template<int PHASE>
__global__ void __launch_bounds__(256, 2)
gemm_nt_bias(const float* __restrict__ A_param,
             const float* __restrict__ B,
             const float* __restrict__ bias1,
             const float* __restrict__ bias2,
             float* __restrict__ C_param,
             int M, int N, int K)
{
    __shared__ __align__(16) float As[BK][BM + 4];
    __shared__ __align__(16) float Bs[BK][BN + 4];

    const float* A = (PHASE == 0) ? A_param : g_hs;
    float*       C = (PHASE == 0) ? g_xp    : C_param;

    const int tid = threadIdx.x;
    const int m0  = blockIdx.y * BM;
    const int n0  = blockIdx.x * BN;
    const int ty  = tid >> 4;    // 0..15 -> rows ty*8..+7
    const int tx  = tid & 15;    // 0..15 -> cols tx*4..+3

    float acc[8][4];
#pragma unroll
    for (int i = 0; i < 8; i++)
#pragma unroll
        for (int j = 0; j < 4; j++) acc[i][j] = 0.f;

    for (int k0 = 0; k0 < K; k0 += BK) {
        // A tile: 128x16 = 512 float4, 2 per thread
#pragma unroll
        for (int it = 0; it < 2; it++) {
            int idx = tid + it * 256;
            int row = idx >> 2, kq = idx & 3;
            float4 v = *(const float4*)(A + (size_t)(m0 + row) * K + k0 + kq * 4);
            As[kq * 4 + 0][row] = v.x;
            As[kq * 4 + 1][row] = v.y;
            As[kq * 4 + 2][row] = v.z;
            As[kq * 4 + 3][row] = v.w;
        }
        // B tile: 64x16 = 256 float4, 1 per thread
        {
            int row = tid >> 2, kq = tid & 3;
            float4 v = *(const float4*)(B + (size_t)(n0 + row) * K + k0 + kq * 4);
            Bs[kq * 4 + 0][row] = v.x;
            Bs[kq * 4 + 1][row] = v.y;
            Bs[kq * 4 + 2][row] = v.z;
            Bs[kq * 4 + 3][row] = v.w;
        }
        __syncthreads();

#pragma unroll
        for (int kk = 0; kk < BK; kk++) {
            float4 a0 = *(const float4*)&As[kk][ty * 8];
            float4 a1 = *(const float4*)&As[kk][ty * 8 + 4];
            float4 bv = *(const float4*)&Bs[kk][tx * 4];
            float av[8] = {a0.x, a0.y, a0.z, a0.w, a1.x, a1.y, a1.z, a1.w};
            float bb[4] = {bv.x, bv.y, bv.z, bv.w};
#pragma unroll
            for (int i = 0; i < 8; i++)
#pragma unroll
                for (int j = 0; j < 4; j++)
                    acc[i][j] += av[i] * bb[j];
        }
        __syncthreads();
    }

    // epilogue: bias + store
    float bsum[4];
#pragma unroll
    for (int j = 0; j < 4; j++) {
        int n = n0 + tx * 4 + j;
        float bv = __ldg(&bias1[n]);
        if (bias2) bv += __ldg(&bias2[n]);
        bsum[j] = bv;
    }
#pragma unroll
    for (int i = 0; i < 8; i++) {
        float4 o;
        o.x = acc[i][0] + bsum[0];
        o.y = acc[i][1] + bsum[1];
        o.z = acc[i][2] + bsum[2];
        o.w = acc[i][3] + bsum[3];
        *(float4*)(C + (size_t)(m0 + ty * 8 + i) * N + n0 + tx * 4) = o;
    }
}

// ---------------- launch ------------------------------------------------
extern "C" void kernel_launch(void* const* d_in, const int* in_sizes, int n_in,
                              void* d_out, int out_size)
{
    const float* x     = (const float*)d_in[0];  // (T,1,H)
    const float* W_ih  = (const float*)d_in[1];  // (H,H)
    const float* W_hh  = (const float*)d_in[2];  // (H,H)
    const float* b_ih  = (const float*)d_in[3];  // (H)
    const float* b_hh  = (const float*)d_in[4];  // (H)
    const float* W_lin = (const float*)d_in[5];  // (O,H)
    const float* b_lin = (const float*)d_in[6];  // (O)
    const float* h0    = (const float*)d_in[7];  // (1,1,H)
    float* out = (float*)d_out;                  // (T,1,O)

    // Phase 1: g_xp = x @ W_ih^T + b_ih + b_hh
    gemm_nt_bias<0><<<dim3(H_DIM / BN, T_STEPS / BM), 256>>>(
        x, W_ih, b_ih, b_hh, nullptr, T_STEPS, H_DIM, H_DIM);

    // Phase 2: sequential recurrence -> g_hs
    rnn_kernel<<<RNN_CTAS, RNN_THREADS>>>(W_hh, h0);

    // Phase 3: out = g_hs @ W_lin^T + b_lin
    gemm_nt_bias<1><<<dim3(O_DIM / BN, T_STEPS / BM), 256>>>(
        nullptr, W_lin, b_lin, nullptr, out, T_STEPS, O_DIM, H_DIM);
}